// round 5
// baseline (speedup 1.0000x reference)
#include <cuda_runtime.h>

// ---------------------------------------------------------------------------
// Problem constants (fixed by setup_inputs)
// ---------------------------------------------------------------------------
#define NLEV 5
#define BATCH 128
#define NBOX 64

static __constant__ int   c_H[NLEV]  = {334, 167, 84, 42, 21};
static __constant__ int   c_W[NLEV]  = {200, 100, 50, 25, 13};
// float32(W/800), float32(H/1333) — matches JAX float32 weak-scalar promotion
static __constant__ float c_sx[NLEV] = {
    (float)(200.0 / 800.0), (float)(100.0 / 800.0), (float)(50.0 / 800.0),
    (float)(25.0 / 800.0),  (float)(13.0 / 800.0)};
static __constant__ float c_sy[NLEV] = {
    (float)(334.0 / 1333.0), (float)(167.0 / 1333.0), (float)(84.0 / 1333.0),
    (float)(42.0 / 1333.0),  (float)(21.0 / 1333.0)};
// float4 counts per level: (128*H*W)/4  (all divisible by 4)
static __constant__ int c_N4[NLEV] = {
    (128 * 334 * 200) / 4, (128 * 167 * 100) / 4, (128 * 84 * 50) / 4,
    (128 * 42 * 25) / 4,   (128 * 21 * 13) / 4};

// Grid layout: 740 = 5 * 148 blocks. Classic placement puts block i and i+148
// on the same SM, so each SM gets one block from each 148-chunk:
//   blocks [0, 592)   : sum blocks  (4 per SM in wave 1)
//   blocks [592, 740) : count blocks (1 per SM in wave 1) — 148 blocks,
//                       each walks tasks j, j+148, ... (< 640)
#define SUM_BLOCKS   592
#define CNT_BLOCKS   148
#define TOTAL_BLOCKS (SUM_BLOCKS + CNT_BLOCKS)   // 740 = 5 waves' worth on occ 5
#define NTASK        (NLEV * BATCH)              // 640
#define THREADS      256

// sum-block partition (proportional to level bytes): 444/111/28/7/2
static __constant__ int c_soff[NLEV + 1] = {0, 444, 555, 583, 590, 592};

// ---------------------------------------------------------------------------
// Scratch: per-block/task partial slots (overwritten every launch -> no
// zeroing needed) + completion ticket for the last-block-done finalize.
// ---------------------------------------------------------------------------
__device__ float        p_sum[SUM_BLOCKS];
__device__ unsigned int p_cnt[NTASK];
__device__ unsigned int g_done;   // zero at load; reset by last block each call

// ---------------------------------------------------------------------------
template <typename T>
__device__ __forceinline__ T block_reduce_sum(T val) {
    __shared__ T sh[32];
    int lane = threadIdx.x & 31;
    int wid  = threadIdx.x >> 5;
#pragma unroll
    for (int o = 16; o > 0; o >>= 1) val += __shfl_down_sync(0xffffffffu, val, o);
    if (lane == 0) sh[wid] = val;
    __syncthreads();
    T r = (threadIdx.x < (unsigned)(blockDim.x >> 5)) ? sh[lane] : T(0);
    if (wid == 0) {
#pragma unroll
        for (int o = 16; o > 0; o >>= 1) r += __shfl_down_sync(0xffffffffu, r, o);
    }
    __syncthreads();   // safe for back-to-back invocations
    return r;
}

__global__ void __launch_bounds__(THREADS)
work_kernel(const float* __restrict__ h0, const float* __restrict__ h1,
            const float* __restrict__ h2, const float* __restrict__ h3,
            const float* __restrict__ h4, const float* __restrict__ boxes,
            float* __restrict__ out) {
    int bx  = blockIdx.x;
    int tid = threadIdx.x;

    if (bx < SUM_BLOCKS) {
        // ---- h reduction with 4-way MLP ----
        int lev = 0;
        while (bx >= c_soff[lev + 1]) lev++;
        int inner = bx - c_soff[lev];
        int nblk  = c_soff[lev + 1] - c_soff[lev];
        const float* hp;
        switch (lev) {
            case 0: hp = h0; break;
            case 1: hp = h1; break;
            case 2: hp = h2; break;
            case 3: hp = h3; break;
            default: hp = h4; break;
        }
        const float4* p = reinterpret_cast<const float4*>(hp);
        int n4     = c_N4[lev];
        int stride = nblk * THREADS;
        int i = inner * THREADS + tid;
        float a0 = 0.0f, a1 = 0.0f, a2 = 0.0f, a3 = 0.0f;
        for (; i + 3 * stride < n4; i += 4 * stride) {
            float4 v0 = p[i];
            float4 v1 = p[i + stride];
            float4 v2 = p[i + 2 * stride];
            float4 v3 = p[i + 3 * stride];
            a0 += (v0.x + v0.y) + (v0.z + v0.w);
            a1 += (v1.x + v1.y) + (v1.z + v1.w);
            a2 += (v2.x + v2.y) + (v2.z + v2.w);
            a3 += (v3.x + v3.y) + (v3.z + v3.w);
        }
        for (; i < n4; i += stride) {
            float4 v = p[i];
            a0 += (v.x + v.y) + (v.z + v.w);
        }
        float s = block_reduce_sum<float>((a0 + a1) + (a2 + a3));
        if (tid == 0) p_sum[bx] = s;
    } else {
        // ---- exact coverage counts: block j handles tasks j, j+148, ... ----
        int j = bx - SUM_BLOCKS;
        __shared__ int s_x1[NBOX], s_x2[NBOX], s_y1[NBOX], s_y2[NBOX];

        for (int task = j; task < NTASK; task += CNT_BLOCKS) {
            int lev = task >> 7;     // /128
            int b   = task & 127;    // %128
            int H = c_H[lev], W = c_W[lev];
            float sx = c_sx[lev], sy = c_sy[lev];

            if (tid < NBOX) {
                const float* bp = boxes + ((size_t)b * NBOX + tid) * 4;
                float fx1 = fminf(fmaxf(rintf(bp[0] * sx), 0.0f), (float)(W - 1));
                float fy1 = fminf(fmaxf(rintf(bp[1] * sy), 0.0f), (float)(H - 1));
                float fx2 = fminf(fmaxf(rintf(bp[2] * sx), 0.0f), (float)W);
                float fy2 = fminf(fmaxf(rintf(bp[3] * sy), 0.0f), (float)H);
                int ix1 = (int)fx1, iy1 = (int)fy1, ix2 = (int)fx2, iy2 = (int)fy2;
                bool valid = (fx2 > fx1) && (fy2 > fy1);
                if (!valid) { iy1 = 0x7fffffff; iy2 = -1; }
                s_x1[tid] = ix1; s_x2[tid] = ix2; s_y1[tid] = iy1; s_y2[tid] = iy2;
            }
            __syncthreads();

            unsigned int cnt = 0;
            for (int r = tid; r < H; r += THREADS) {
                unsigned int w[7] = {0, 0, 0, 0, 0, 0, 0};
#pragma unroll 4
                for (int m = 0; m < NBOX; m++) {
                    if (r >= s_y1[m] && r < s_y2[m]) {
                        int a = s_x1[m], e = s_x2[m];
#pragma unroll
                        for (int wi = 0; wi < 7; wi++) {
                            int lo = a - wi * 32;
                            int hi = e - wi * 32;
                            lo = lo < 0 ? 0 : lo;
                            hi = hi > 32 ? 32 : hi;
                            if (hi > lo) {
                                unsigned int hm =
                                    (hi == 32) ? 0xFFFFFFFFu : ((1u << hi) - 1u);
                                w[wi] |= hm & (0xFFFFFFFFu << lo);
                            }
                        }
                    }
                }
#pragma unroll
                for (int wi = 0; wi < 7; wi++) cnt += (unsigned)__popc(w[wi]);
            }
            cnt = block_reduce_sum<unsigned int>(cnt);  // ends with syncthreads
            if (tid == 0) p_cnt[task] = cnt;
            __syncthreads();   // protect shared box arrays before next task
        }
    }

    // ---- completion ticket: last block finalizes ----
    __shared__ bool is_last;
    __threadfence();                       // release partial writes
    if (tid == 0) {
        unsigned int v = atomicAdd(&g_done, 1u);
        is_last = (v == TOTAL_BLOCKS - 1);
    }
    __syncthreads();
    if (!is_last) return;
    __threadfence();                       // acquire other blocks' partials

    // 5 warps reduce the 5 levels in parallel (double accumulation).
    __shared__ double s_d2[NLEV];
    int wid  = tid >> 5;
    int lane = tid & 31;
    if (wid < NLEV) {
        int lev = wid;
        double s = 0.0;
        for (int i = c_soff[lev] + lane; i < c_soff[lev + 1]; i += 32)
            s += (double)p_sum[i];
        unsigned int c = 0;
        for (int i = lane; i < BATCH; i += 32)
            c += p_cnt[lev * BATCH + i];
#pragma unroll
        for (int o = 16; o > 0; o >>= 1) {
            s += __shfl_down_sync(0xffffffffu, s, o);
            c += __shfl_down_sync(0xffffffffu, c, o);
        }
        if (lane == 0) {
            double tn = (double)BATCH * (double)c_H[lev] * (double)c_W[lev];
            double d  = s / tn - (double)c / tn;
            s_d2[lev] = d * d;
        }
    }
    __syncthreads();
    if (tid == 0) {
        double acc = s_d2[0] + s_d2[1] + s_d2[2] + s_d2[3] + s_d2[4];
        out[0] = (float)(acc / (double)NLEV);
        atomicExch(&g_done, 0u);           // reset ticket for next replay
    }
}

// ---------------------------------------------------------------------------
extern "C" void kernel_launch(void* const* d_in, const int* in_sizes, int n_in,
                              void* d_out, int out_size) {
    (void)in_sizes; (void)n_in; (void)out_size;
    const float* h0    = (const float*)d_in[0];
    const float* h1    = (const float*)d_in[1];
    const float* h2    = (const float*)d_in[2];
    const float* h3    = (const float*)d_in[3];
    const float* h4    = (const float*)d_in[4];
    const float* boxes = (const float*)d_in[5];
    float* out = (float*)d_out;

    work_kernel<<<TOTAL_BLOCKS, THREADS>>>(h0, h1, h2, h3, h4, boxes, out);
}

// round 6
// speedup vs baseline: 2.0392x; 2.0392x over previous
#include <cuda_runtime.h>

// ---------------------------------------------------------------------------
// Problem constants (fixed by setup_inputs)
// ---------------------------------------------------------------------------
#define NLEV 5
#define BATCH 128
#define NBOX 64

static __constant__ int c_Hc[NLEV] = {334, 167, 84, 42, 21};
static __constant__ int c_Wc[NLEV] = {200, 100, 50, 25, 13};
// float4 counts per level: (128*H*W)/4  (all divisible by 4)
static __constant__ int c_N4[NLEV] = {
    (128 * 334 * 200) / 4, (128 * 167 * 100) / 4, (128 * 84 * 50) / 4,
    (128 * 42 * 25) / 4,   (128 * 21 * 13) / 4};

// Single-wave grid: 8 blocks/SM * 148 SMs = 1184 resident blocks.
//   blocks [0, 544)    : sum blocks (grid-stride over all levels)
//   blocks [544, 1184) : count blocks, ONE (level,batch) task each (640)
#define SUM_BLOCKS   544
#define CNT_BLOCKS   (NLEV * BATCH)              // 640
#define TOTAL_BLOCKS (SUM_BLOCKS + CNT_BLOCKS)   // 1184 = one full wave
#define THREADS      256

// ---------------------------------------------------------------------------
// Scratch (overwritten every launch -> no zeroing) + completion ticket.
// ---------------------------------------------------------------------------
__device__ float        p_sum[NLEV * SUM_BLOCKS];  // level-major
__device__ unsigned int p_cnt[CNT_BLOCKS];
__device__ unsigned int g_done;   // zero at load; reset by last block each call

// ---------------------------------------------------------------------------
template <typename T>
__device__ __forceinline__ T block_reduce_sum(T val) {
    __shared__ T sh[32];
    int lane = threadIdx.x & 31;
    int wid  = threadIdx.x >> 5;
#pragma unroll
    for (int o = 16; o > 0; o >>= 1) val += __shfl_down_sync(0xffffffffu, val, o);
    if (lane == 0) sh[wid] = val;
    __syncthreads();
    T r = (threadIdx.x < (unsigned)(blockDim.x >> 5)) ? sh[lane] : T(0);
    if (wid == 0) {
#pragma unroll
        for (int o = 16; o > 0; o >>= 1) r += __shfl_down_sync(0xffffffffu, r, o);
    }
    __syncthreads();   // safe for back-to-back invocations
    return r;
}

// ---------------------------------------------------------------------------
// Exact union-coverage pixel count for one (level, batch) pair.
// All level geometry is compile-time: word count NW, scales, clamps.
// ---------------------------------------------------------------------------
template <int H, int W>
__device__ __forceinline__ unsigned int do_count(const float* __restrict__ boxes,
                                                 int b) {
    constexpr int   NW = (W + 31) / 32;
    constexpr float sx = (float)(W / 800.0);     // float32(W/800)
    constexpr float sy = (float)(H / 1333.0);    // float32(H/1333)

    __shared__ int s_x1[NBOX], s_x2[NBOX], s_y1[NBOX], s_y2[NBOX];
    int tid = threadIdx.x;
    if (tid < NBOX) {
        const float* bp = boxes + ((size_t)b * NBOX + tid) * 4;
        float fx1 = fminf(fmaxf(rintf(bp[0] * sx), 0.0f), (float)(W - 1));
        float fy1 = fminf(fmaxf(rintf(bp[1] * sy), 0.0f), (float)(H - 1));
        float fx2 = fminf(fmaxf(rintf(bp[2] * sx), 0.0f), (float)W);
        float fy2 = fminf(fmaxf(rintf(bp[3] * sy), 0.0f), (float)H);
        int ix1 = (int)fx1, iy1 = (int)fy1, ix2 = (int)fx2, iy2 = (int)fy2;
        bool valid = (fx2 > fx1) && (fy2 > fy1);
        if (!valid) { iy1 = 0x7fffffff; iy2 = -1; }
        s_x1[tid] = ix1; s_x2[tid] = ix2; s_y1[tid] = iy1; s_y2[tid] = iy2;
    }
    __syncthreads();

    unsigned int cnt = 0;
    for (int r = tid; r < H; r += THREADS) {
        unsigned int w[NW];
#pragma unroll
        for (int wi = 0; wi < NW; wi++) w[wi] = 0u;
#pragma unroll 4
        for (int m = 0; m < NBOX; m++) {
            if (r >= s_y1[m] && r < s_y2[m]) {
                int a = s_x1[m], e = s_x2[m];
#pragma unroll
                for (int wi = 0; wi < NW; wi++) {
                    int lo = a - wi * 32;
                    int hi = e - wi * 32;
                    lo = lo < 0 ? 0 : lo;
                    hi = hi > 32 ? 32 : hi;
                    if (hi > lo) {
                        unsigned int hm =
                            (hi == 32) ? 0xFFFFFFFFu : ((1u << hi) - 1u);
                        w[wi] |= hm & (0xFFFFFFFFu << lo);
                    }
                }
            }
        }
#pragma unroll
        for (int wi = 0; wi < NW; wi++) cnt += (unsigned)__popc(w[wi]);
    }
    return cnt;
}

// ---------------------------------------------------------------------------
__global__ void __launch_bounds__(THREADS, 8)
work_kernel(const float* __restrict__ h0, const float* __restrict__ h1,
            const float* __restrict__ h2, const float* __restrict__ h3,
            const float* __restrict__ h4, const float* __restrict__ boxes,
            float* __restrict__ out) {
    int bx  = blockIdx.x;
    int tid = threadIdx.x;

    if (bx < SUM_BLOCKS) {
        // ---- h reduction: every sum block grid-strides over every level ----
        const float* hps[NLEV] = {h0, h1, h2, h3, h4};
        const int stride = SUM_BLOCKS * THREADS;
        const int base   = bx * THREADS + tid;
#pragma unroll
        for (int lev = 0; lev < NLEV; lev++) {
            const float4* p = reinterpret_cast<const float4*>(hps[lev]);
            int n4 = c_N4[lev];
            float a0 = 0.0f, a1 = 0.0f, a2 = 0.0f, a3 = 0.0f;
            int i = base;
            for (; i + 3 * stride < n4; i += 4 * stride) {
                float4 v0 = p[i];
                float4 v1 = p[i + stride];
                float4 v2 = p[i + 2 * stride];
                float4 v3 = p[i + 3 * stride];
                a0 += (v0.x + v0.y) + (v0.z + v0.w);
                a1 += (v1.x + v1.y) + (v1.z + v1.w);
                a2 += (v2.x + v2.y) + (v2.z + v2.w);
                a3 += (v3.x + v3.y) + (v3.z + v3.w);
            }
            for (; i < n4; i += stride) {
                float4 v = p[i];
                a0 += (v.x + v.y) + (v.z + v.w);
            }
            float s = block_reduce_sum<float>((a0 + a1) + (a2 + a3));
            if (tid == 0) p_sum[lev * SUM_BLOCKS + bx] = s;
        }
    } else {
        // ---- exact coverage count: one block per (level, batch) ----
        int task = bx - SUM_BLOCKS;
        int lev  = task >> 7;     // /128
        int b    = task & 127;    // %128
        unsigned int cnt;
        switch (lev) {
            case 0:  cnt = do_count<334, 200>(boxes, b); break;
            case 1:  cnt = do_count<167, 100>(boxes, b); break;
            case 2:  cnt = do_count<84, 50>(boxes, b);   break;
            case 3:  cnt = do_count<42, 25>(boxes, b);   break;
            default: cnt = do_count<21, 13>(boxes, b);   break;
        }
        cnt = block_reduce_sum<unsigned int>(cnt);
        if (tid == 0) p_cnt[task] = cnt;
    }

    // ---- completion ticket: last block finalizes ----
    __shared__ bool is_last;
    __threadfence();                       // release partial writes
    if (tid == 0) {
        unsigned int v = atomicAdd(&g_done, 1u);
        is_last = (v == TOTAL_BLOCKS - 1);
    }
    __syncthreads();
    if (!is_last) return;
    __threadfence();                       // acquire other blocks' partials

    // 5 warps reduce the 5 levels in parallel (double accumulation).
    __shared__ double s_d2[NLEV];
    int wid  = tid >> 5;
    int lane = tid & 31;
    if (wid < NLEV) {
        int lev = wid;
        double s = 0.0;
        for (int i = lane; i < SUM_BLOCKS; i += 32)
            s += (double)p_sum[lev * SUM_BLOCKS + i];
        unsigned int c = 0;
        for (int i = lane; i < BATCH; i += 32)
            c += p_cnt[lev * BATCH + i];
#pragma unroll
        for (int o = 16; o > 0; o >>= 1) {
            s += __shfl_down_sync(0xffffffffu, s, o);
            c += __shfl_down_sync(0xffffffffu, c, o);
        }
        if (lane == 0) {
            double tn = (double)BATCH * (double)c_Hc[lev] * (double)c_Wc[lev];
            double d  = s / tn - (double)c / tn;
            s_d2[lev] = d * d;
        }
    }
    __syncthreads();
    if (tid == 0) {
        double acc = s_d2[0] + s_d2[1] + s_d2[2] + s_d2[3] + s_d2[4];
        out[0] = (float)(acc / (double)NLEV);
        atomicExch(&g_done, 0u);           // reset ticket for next replay
    }
}

// ---------------------------------------------------------------------------
extern "C" void kernel_launch(void* const* d_in, const int* in_sizes, int n_in,
                              void* d_out, int out_size) {
    (void)in_sizes; (void)n_in; (void)out_size;
    const float* h0    = (const float*)d_in[0];
    const float* h1    = (const float*)d_in[1];
    const float* h2    = (const float*)d_in[2];
    const float* h3    = (const float*)d_in[3];
    const float* h4    = (const float*)d_in[4];
    const float* boxes = (const float*)d_in[5];
    float* out = (float*)d_out;

    work_kernel<<<TOTAL_BLOCKS, THREADS>>>(h0, h1, h2, h3, h4, boxes, out);
}

// round 7
// speedup vs baseline: 2.6036x; 1.2768x over previous
#include <cuda_runtime.h>

#define NLEV 5
#define BATCH 128
#define NBOX 64

static __constant__ int c_Hc[NLEV] = {334, 167, 84, 42, 21};
static __constant__ int c_Wc[NLEV] = {200, 100, 50, 25, 13};
// float4 counts per level: (128*H*W)/4
static __constant__ int c_N4[NLEV] = {
    (128 * 334 * 200) / 4, (128 * 167 * 100) / 4, (128 * 84 * 50) / 4,
    (128 * 42 * 25) / 4,   (128 * 21 * 13) / 4};

// One full wave: 8 blocks/SM * 148 SMs. ALL blocks do a sum slice;
// blocks [0, 640) additionally do one (level,batch) count task.
#define CNT_BLOCKS   (NLEV * BATCH)   // 640
#define TOTAL_BLOCKS 1184
#define THREADS      256
#define NWARP        (THREADS / 32)

__device__ float        p_sum[NLEV * TOTAL_BLOCKS];
__device__ unsigned int p_cnt[CNT_BLOCKS];
__device__ unsigned int g_done;   // zero at load; reset by last block

// ---------------------------------------------------------------------------
template <typename T>
__device__ __forceinline__ T block_reduce_sum(T val) {
    __shared__ T sh[32];
    int lane = threadIdx.x & 31;
    int wid  = threadIdx.x >> 5;
#pragma unroll
    for (int o = 16; o > 0; o >>= 1) val += __shfl_down_sync(0xffffffffu, val, o);
    if (lane == 0) sh[wid] = val;
    __syncthreads();
    T r = (threadIdx.x < (unsigned)NWARP) ? sh[lane] : T(0);
    if (wid == 0) {
#pragma unroll
        for (int o = 16; o > 0; o >>= 1) r += __shfl_down_sync(0xffffffffu, r, o);
    }
    __syncthreads();
    return r;
}

// ---------------------------------------------------------------------------
// Exact union-coverage count with precomputed per-box x-masks and per-row
// active-box bitmaps (shared atomicOr). Per row: load 64-bit bitmap, iterate
// set bits only, OR precomputed words, popcount.
// Shared layout in sb (u32): [0,64*STRIDE) x-masks | act_lo[H] | act_hi[H]
// ---------------------------------------------------------------------------
template <int H, int W>
__device__ __forceinline__ unsigned int do_count(const float* __restrict__ boxes,
                                                 int b, unsigned int* sb) {
    constexpr int   NW     = (W + 31) / 32;
    constexpr int   STRIDE = (NW | 1);               // odd -> conflict-free gather
    constexpr float sx     = (float)(W / 800.0);     // float32(W/800)
    constexpr float sy     = (float)(H / 1333.0);    // float32(H/1333)

    unsigned int* s_xm = sb;
    unsigned int* s_lo = sb + NBOX * STRIDE;
    unsigned int* s_hi = s_lo + H;
    int tid = threadIdx.x;

    // zero the 2*H bitmap words
    for (int i = tid; i < 2 * H; i += THREADS) s_lo[i] = 0u;
    __syncthreads();

    if (tid < NBOX) {
        const float* bp = boxes + ((size_t)b * NBOX + tid) * 4;
        float fx1 = fminf(fmaxf(rintf(bp[0] * sx), 0.0f), (float)(W - 1));
        float fy1 = fminf(fmaxf(rintf(bp[1] * sy), 0.0f), (float)(H - 1));
        float fx2 = fminf(fmaxf(rintf(bp[2] * sx), 0.0f), (float)W);
        float fy2 = fminf(fmaxf(rintf(bp[3] * sy), 0.0f), (float)H);
        int ix1 = (int)fx1, iy1 = (int)fy1, ix2 = (int)fx2, iy2 = (int)fy2;
        bool valid = (fx2 > fx1) && (fy2 > fy1);

        // per-box x-mask words (row-independent)
#pragma unroll
        for (int wi = 0; wi < NW; wi++) {
            int lo = ix1 - wi * 32;
            int hi = ix2 - wi * 32;
            lo = lo < 0 ? 0 : lo;
            hi = hi > 32 ? 32 : hi;
            unsigned int wmask = 0u;
            if (hi > lo) {
                unsigned int hm = (hi == 32) ? 0xFFFFFFFFu : ((1u << hi) - 1u);
                wmask = hm & (0xFFFFFFFFu << lo);
            }
            s_xm[tid * STRIDE + wi] = wmask;
        }

        // mark this box active in its row interval
        if (valid) {
            unsigned int  bit = 1u << (tid & 31);
            unsigned int* tgt = (tid < 32) ? s_lo : s_hi;
            for (int r = iy1; r < iy2; r++) atomicOr(&tgt[r], bit);
        }
    }
    __syncthreads();

    unsigned int cnt = 0;
    for (int r = tid; r < H; r += THREADS) {
        unsigned int w[NW];
#pragma unroll
        for (int wi = 0; wi < NW; wi++) w[wi] = 0u;
        unsigned int mlo = s_lo[r];
        unsigned int mhi = s_hi[r];
        while (mlo) {
            int m = __ffs(mlo) - 1;
            mlo &= mlo - 1;
            const unsigned int* bm = &s_xm[m * STRIDE];
#pragma unroll
            for (int wi = 0; wi < NW; wi++) w[wi] |= bm[wi];
        }
        while (mhi) {
            int m = __ffs(mhi) - 1 + 32;
            mhi &= mhi - 1;
            const unsigned int* bm = &s_xm[m * STRIDE];
#pragma unroll
            for (int wi = 0; wi < NW; wi++) w[wi] |= bm[wi];
        }
#pragma unroll
        for (int wi = 0; wi < NW; wi++) cnt += (unsigned)__popc(w[wi]);
    }
    __syncthreads();   // protect shared buffer (paranoia for reuse)
    return cnt;
}

// shared scratch for do_count: max across levels of 64*STRIDE + 2*H
// level0: 64*7 + 668 = 1116 u32
__device__ __forceinline__ unsigned int* cnt_smem() {
    static __shared__ unsigned int buf[1120];
    return buf;
}

// ---------------------------------------------------------------------------
__global__ void __launch_bounds__(THREADS, 8)
work_kernel(const float* __restrict__ h0, const float* __restrict__ h1,
            const float* __restrict__ h2, const float* __restrict__ h3,
            const float* __restrict__ h4, const float* __restrict__ boxes,
            float* __restrict__ out) {
    int bx  = blockIdx.x;
    int tid = threadIdx.x;
    int lane = tid & 31;
    int wid  = tid >> 5;

    // ================= sum phase: every block takes a slice ================
    {
        const float* hps[NLEV] = {h0, h1, h2, h3, h4};
        const int stride = TOTAL_BLOCKS * THREADS;
        const int base   = bx * THREADS + tid;
        float slev[NLEV];
#pragma unroll
        for (int lev = 0; lev < NLEV; lev++) {
            const float4* p = reinterpret_cast<const float4*>(hps[lev]);
            int n4 = c_N4[lev];
            float a0 = 0.0f, a1 = 0.0f, a2 = 0.0f, a3 = 0.0f;
            int i = base;
            for (; i + 3 * stride < n4; i += 4 * stride) {
                float4 v0 = p[i];
                float4 v1 = p[i + stride];
                float4 v2 = p[i + 2 * stride];
                float4 v3 = p[i + 3 * stride];
                a0 += (v0.x + v0.y) + (v0.z + v0.w);
                a1 += (v1.x + v1.y) + (v1.z + v1.w);
                a2 += (v2.x + v2.y) + (v2.z + v2.w);
                a3 += (v3.x + v3.y) + (v3.z + v3.w);
            }
            for (; i < n4; i += stride) {
                float4 v = p[i];
                a0 += (v.x + v.y) + (v.z + v.w);
            }
            slev[lev] = (a0 + a1) + (a2 + a3);
        }

        // single fused block reduction of 5 values (2 barriers total)
        __shared__ float sred[NWARP][NLEV];
#pragma unroll
        for (int l = 0; l < NLEV; l++) {
#pragma unroll
            for (int o = 16; o > 0; o >>= 1)
                slev[l] += __shfl_down_sync(0xffffffffu, slev[l], o);
        }
        if (lane == 0) {
#pragma unroll
            for (int l = 0; l < NLEV; l++) sred[wid][l] = slev[l];
        }
        __syncthreads();
        if (wid == 0) {
            float v[NLEV];
#pragma unroll
            for (int l = 0; l < NLEV; l++)
                v[l] = (lane < NWARP) ? sred[lane][l] : 0.0f;
#pragma unroll
            for (int l = 0; l < NLEV; l++) {
#pragma unroll
                for (int o = 4; o > 0; o >>= 1)
                    v[l] += __shfl_down_sync(0xffffffffu, v[l], o);
            }
            if (lane == 0) {
#pragma unroll
                for (int l = 0; l < NLEV; l++)
                    p_sum[l * TOTAL_BLOCKS + bx] = v[l];
            }
        }
        __syncthreads();
    }

    // ================= count phase: blocks [0, 640) =======================
    if (bx < CNT_BLOCKS) {
        int lev = bx >> 7;     // /128
        int b   = bx & 127;    // %128
        unsigned int* sb = cnt_smem();
        unsigned int cnt;
        switch (lev) {
            case 0:  cnt = do_count<334, 200>(boxes, b, sb); break;
            case 1:  cnt = do_count<167, 100>(boxes, b, sb); break;
            case 2:  cnt = do_count<84, 50>(boxes, b, sb);   break;
            case 3:  cnt = do_count<42, 25>(boxes, b, sb);   break;
            default: cnt = do_count<21, 13>(boxes, b, sb);   break;
        }
        cnt = block_reduce_sum<unsigned int>(cnt);
        if (tid == 0) p_cnt[bx] = cnt;
    }

    // ================= completion ticket -> finalize ======================
    __shared__ bool is_last;
    __threadfence();
    if (tid == 0) {
        unsigned int v = atomicAdd(&g_done, 1u);
        is_last = (v == TOTAL_BLOCKS - 1);
    }
    __syncthreads();
    if (!is_last) return;
    __threadfence();

    __shared__ double s_d2[NLEV];
    if (wid < NLEV) {
        int lev = wid;
        double s = 0.0;
        for (int i = lane; i < TOTAL_BLOCKS; i += 32)
            s += (double)p_sum[lev * TOTAL_BLOCKS + i];
        unsigned int c = 0;
        for (int i = lane; i < BATCH; i += 32)
            c += p_cnt[lev * BATCH + i];
#pragma unroll
        for (int o = 16; o > 0; o >>= 1) {
            s += __shfl_down_sync(0xffffffffu, s, o);
            c += __shfl_down_sync(0xffffffffu, c, o);
        }
        if (lane == 0) {
            double tn = (double)BATCH * (double)c_Hc[lev] * (double)c_Wc[lev];
            double d  = s / tn - (double)c / tn;
            s_d2[lev] = d * d;
        }
    }
    __syncthreads();
    if (tid == 0) {
        double acc = s_d2[0] + s_d2[1] + s_d2[2] + s_d2[3] + s_d2[4];
        out[0] = (float)(acc / (double)NLEV);
        atomicExch(&g_done, 0u);   // reset ticket for next replay
    }
}

// ---------------------------------------------------------------------------
extern "C" void kernel_launch(void* const* d_in, const int* in_sizes, int n_in,
                              void* d_out, int out_size) {
    (void)in_sizes; (void)n_in; (void)out_size;
    const float* h0    = (const float*)d_in[0];
    const float* h1    = (const float*)d_in[1];
    const float* h2    = (const float*)d_in[2];
    const float* h3    = (const float*)d_in[3];
    const float* h4    = (const float*)d_in[4];
    const float* boxes = (const float*)d_in[5];
    float* out = (float*)d_out;

    work_kernel<<<TOTAL_BLOCKS, THREADS>>>(h0, h1, h2, h3, h4, boxes, out);
}

// round 8
// speedup vs baseline: 2.8537x; 1.0960x over previous
#include <cuda_runtime.h>

#define NLEV 5
#define BATCH 128
#define NBOX 64

static __constant__ int c_Hc[NLEV] = {334, 167, 84, 42, 21};
static __constant__ int c_Wc[NLEV] = {200, 100, 50, 25, 13};

// float4 counts per level: (128*H*W)/4
#define N4_0 2137600
#define N4_1 534400
#define N4_2 134400
#define N4_3 33600
#define N4_4 8736

// Per-warp span: 10 unrolled lane-loads * 32 lanes = 320 float4 = 5 KB.
#define ULOADS 10
#define WARP_SPAN (32 * ULOADS)
// warp-range starts per level (N4 / 320, exact for levels 0-3)
#define WS0 0
#define WS1 6680
#define WS2 8350
#define WS3 8770
#define WS4 8875
#define WSE 8903   // level-4 end (last warp partial)

// One full wave: 8 blocks/SM * 148 SMs.
#define CNT_BLOCKS   (NLEV * BATCH)   // 640
#define TOTAL_BLOCKS 1184             // 9472 warps >= 8903 sum warps
#define THREADS      256
#define NWARP        (THREADS / 32)

__device__ float        p_sum[NLEV * TOTAL_BLOCKS];
__device__ unsigned int p_cnt[CNT_BLOCKS];
__device__ unsigned int g_done;   // zero at load; reset by last block

// ---------------------------------------------------------------------------
template <typename T>
__device__ __forceinline__ T block_reduce_sum(T val) {
    __shared__ T sh[32];
    int lane = threadIdx.x & 31;
    int wid  = threadIdx.x >> 5;
#pragma unroll
    for (int o = 16; o > 0; o >>= 1) val += __shfl_down_sync(0xffffffffu, val, o);
    if (lane == 0) sh[wid] = val;
    __syncthreads();
    T r = (threadIdx.x < (unsigned)NWARP) ? sh[lane] : T(0);
    if (wid == 0) {
#pragma unroll
        for (int o = 16; o > 0; o >>= 1) r += __shfl_down_sync(0xffffffffu, r, o);
    }
    __syncthreads();
    return r;
}

// ---------------------------------------------------------------------------
// Exact union-coverage count (round-7 scheme: precomputed per-box x-masks +
// per-row active-box bitmaps via shared atomicOr, then ffs-driven OR).
// ---------------------------------------------------------------------------
template <int H, int W>
__device__ __forceinline__ unsigned int do_count(const float* __restrict__ boxes,
                                                 int b, unsigned int* sb) {
    constexpr int   NW     = (W + 31) / 32;
    constexpr int   STRIDE = (NW | 1);
    constexpr float sx     = (float)(W / 800.0);
    constexpr float sy     = (float)(H / 1333.0);

    unsigned int* s_xm = sb;
    unsigned int* s_lo = sb + NBOX * STRIDE;
    unsigned int* s_hi = s_lo + H;
    int tid = threadIdx.x;

    for (int i = tid; i < 2 * H; i += THREADS) s_lo[i] = 0u;
    __syncthreads();

    if (tid < NBOX) {
        const float* bp = boxes + ((size_t)b * NBOX + tid) * 4;
        float fx1 = fminf(fmaxf(rintf(bp[0] * sx), 0.0f), (float)(W - 1));
        float fy1 = fminf(fmaxf(rintf(bp[1] * sy), 0.0f), (float)(H - 1));
        float fx2 = fminf(fmaxf(rintf(bp[2] * sx), 0.0f), (float)W);
        float fy2 = fminf(fmaxf(rintf(bp[3] * sy), 0.0f), (float)H);
        int ix1 = (int)fx1, iy1 = (int)fy1, ix2 = (int)fx2, iy2 = (int)fy2;
        bool valid = (fx2 > fx1) && (fy2 > fy1);

#pragma unroll
        for (int wi = 0; wi < NW; wi++) {
            int lo = ix1 - wi * 32;
            int hi = ix2 - wi * 32;
            lo = lo < 0 ? 0 : lo;
            hi = hi > 32 ? 32 : hi;
            unsigned int wmask = 0u;
            if (hi > lo) {
                unsigned int hm = (hi == 32) ? 0xFFFFFFFFu : ((1u << hi) - 1u);
                wmask = hm & (0xFFFFFFFFu << lo);
            }
            s_xm[tid * STRIDE + wi] = wmask;
        }

        if (valid) {
            unsigned int  bit = 1u << (tid & 31);
            unsigned int* tgt = (tid < 32) ? s_lo : s_hi;
            for (int r = iy1; r < iy2; r++) atomicOr(&tgt[r], bit);
        }
    }
    __syncthreads();

    unsigned int cnt = 0;
    for (int r = tid; r < H; r += THREADS) {
        unsigned int w[NW];
#pragma unroll
        for (int wi = 0; wi < NW; wi++) w[wi] = 0u;
        unsigned int mlo = s_lo[r];
        unsigned int mhi = s_hi[r];
        while (mlo) {
            int m = __ffs(mlo) - 1;
            mlo &= mlo - 1;
            const unsigned int* bm = &s_xm[m * STRIDE];
#pragma unroll
            for (int wi = 0; wi < NW; wi++) w[wi] |= bm[wi];
        }
        while (mhi) {
            int m = __ffs(mhi) - 1 + 32;
            mhi &= mhi - 1;
            const unsigned int* bm = &s_xm[m * STRIDE];
#pragma unroll
            for (int wi = 0; wi < NW; wi++) w[wi] |= bm[wi];
        }
#pragma unroll
        for (int wi = 0; wi < NW; wi++) cnt += (unsigned)__popc(w[wi]);
    }
    __syncthreads();
    return cnt;
}

__device__ __forceinline__ unsigned int* cnt_smem() {
    static __shared__ unsigned int buf[1120];
    return buf;
}

// ---------------------------------------------------------------------------
__global__ void __launch_bounds__(THREADS, 8)
work_kernel(const float* __restrict__ h0, const float* __restrict__ h1,
            const float* __restrict__ h2, const float* __restrict__ h3,
            const float* __restrict__ h4, const float* __restrict__ boxes,
            float* __restrict__ out) {
    int bx   = blockIdx.x;
    int tid  = threadIdx.x;
    int lane = tid & 31;
    int wid  = tid >> 5;

    // ============ sum phase: static contiguous per-warp partition ==========
    __shared__ float s_wsum[NWARP];
    __shared__ int   s_wlev[NWARP];
    {
        int g = bx * NWARP + wid;      // global warp id
        float s = 0.0f;
        int lev = -1;
        if (g < WSE) {
            lev = (g < WS1) ? 0 : (g < WS2) ? 1 : (g < WS3) ? 2
                : (g < WS4) ? 3 : 4;
            const float* hp = (lev == 0) ? h0 : (lev == 1) ? h1
                            : (lev == 2) ? h2 : (lev == 3) ? h3 : h4;
            int start = (lev == 0) ? WS0 : (lev == 1) ? WS1
                      : (lev == 2) ? WS2 : (lev == 3) ? WS3 : WS4;
            int n4    = (lev == 0) ? N4_0 : (lev == 1) ? N4_1
                      : (lev == 2) ? N4_2 : (lev == 3) ? N4_3 : N4_4;
            const float4* p = reinterpret_cast<const float4*>(hp);
            int idx0 = (g - start) * WARP_SPAN + lane;
            float a0 = 0.0f, a1 = 0.0f, a2 = 0.0f, a3 = 0.0f;
#pragma unroll
            for (int u = 0; u < ULOADS; u += 2) {
                int i0 = idx0 + u * 32;
                int i1 = idx0 + (u + 1) * 32;
                float4 v0 = (i0 < n4) ? p[i0] : make_float4(0.f, 0.f, 0.f, 0.f);
                float4 v1 = (i1 < n4) ? p[i1] : make_float4(0.f, 0.f, 0.f, 0.f);
                a0 += v0.x + v0.y;
                a1 += v0.z + v0.w;
                a2 += v1.x + v1.y;
                a3 += v1.z + v1.w;
            }
            s = (a0 + a1) + (a2 + a3);
#pragma unroll
            for (int o = 16; o > 0; o >>= 1)
                s += __shfl_down_sync(0xffffffffu, s, o);
        }
        if (lane == 0) { s_wsum[wid] = s; s_wlev[wid] = lev; }
        __syncthreads();
        if (tid == 0) {
            float acc0 = 0.f, acc1 = 0.f, acc2 = 0.f, acc3 = 0.f, acc4 = 0.f;
#pragma unroll
            for (int w2 = 0; w2 < NWARP; w2++) {
                int   l = s_wlev[w2];
                float v = s_wsum[w2];
                acc0 += (l == 0) ? v : 0.f;
                acc1 += (l == 1) ? v : 0.f;
                acc2 += (l == 2) ? v : 0.f;
                acc3 += (l == 3) ? v : 0.f;
                acc4 += (l == 4) ? v : 0.f;
            }
            p_sum[0 * TOTAL_BLOCKS + bx] = acc0;
            p_sum[1 * TOTAL_BLOCKS + bx] = acc1;
            p_sum[2 * TOTAL_BLOCKS + bx] = acc2;
            p_sum[3 * TOTAL_BLOCKS + bx] = acc3;
            p_sum[4 * TOTAL_BLOCKS + bx] = acc4;
        }
    }

    // ============ count phase: blocks [0, 640) =============================
    if (bx < CNT_BLOCKS) {
        int lev = bx >> 7;
        int b   = bx & 127;
        unsigned int* sb = cnt_smem();
        unsigned int cnt;
        switch (lev) {
            case 0:  cnt = do_count<334, 200>(boxes, b, sb); break;
            case 1:  cnt = do_count<167, 100>(boxes, b, sb); break;
            case 2:  cnt = do_count<84, 50>(boxes, b, sb);   break;
            case 3:  cnt = do_count<42, 25>(boxes, b, sb);   break;
            default: cnt = do_count<21, 13>(boxes, b, sb);   break;
        }
        cnt = block_reduce_sum<unsigned int>(cnt);
        if (tid == 0) p_cnt[bx] = cnt;
    }

    // ============ completion ticket -> finalize ============================
    __shared__ bool is_last;
    __threadfence();
    if (tid == 0) {
        unsigned int v = atomicAdd(&g_done, 1u);
        is_last = (v == TOTAL_BLOCKS - 1);
    }
    __syncthreads();
    if (!is_last) return;
    __threadfence();

    __shared__ double s_d2[NLEV];
    if (wid < NLEV) {
        int lev = wid;
        double s = 0.0;
        for (int i = lane; i < TOTAL_BLOCKS; i += 32)
            s += (double)p_sum[lev * TOTAL_BLOCKS + i];
        unsigned int c = 0;
        for (int i = lane; i < BATCH; i += 32)
            c += p_cnt[lev * BATCH + i];
#pragma unroll
        for (int o = 16; o > 0; o >>= 1) {
            s += __shfl_down_sync(0xffffffffu, s, o);
            c += __shfl_down_sync(0xffffffffu, c, o);
        }
        if (lane == 0) {
            double tn = (double)BATCH * (double)c_Hc[lev] * (double)c_Wc[lev];
            double d  = s / tn - (double)c / tn;
            s_d2[lev] = d * d;
        }
    }
    __syncthreads();
    if (tid == 0) {
        double acc = s_d2[0] + s_d2[1] + s_d2[2] + s_d2[3] + s_d2[4];
        out[0] = (float)(acc / (double)NLEV);
        atomicExch(&g_done, 0u);
    }
}

// ---------------------------------------------------------------------------
extern "C" void kernel_launch(void* const* d_in, const int* in_sizes, int n_in,
                              void* d_out, int out_size) {
    (void)in_sizes; (void)n_in; (void)out_size;
    const float* h0    = (const float*)d_in[0];
    const float* h1    = (const float*)d_in[1];
    const float* h2    = (const float*)d_in[2];
    const float* h3    = (const float*)d_in[3];
    const float* h4    = (const float*)d_in[4];
    const float* boxes = (const float*)d_in[5];
    float* out = (float*)d_out;

    work_kernel<<<TOTAL_BLOCKS, THREADS>>>(h0, h1, h2, h3, h4, boxes, out);
}